// round 3
// baseline (speedup 1.0000x reference)
#include <cuda_runtime.h>

#define TSEQ 1024
#define BATCH 4096
#define KTANH 2.885390081777927f   // 2/ln(2): ex2(KTANH*x) = exp(2x)

__device__ __forceinline__ float ex2_approx(float x) {
    float y; asm("ex2.approx.f32 %0, %1;" : "=f"(y) : "f"(x)); return y;
}
__device__ __forceinline__ float rcp_approx(float x) {
    float y; asm("rcp.approx.f32 %0, %1;" : "=f"(y) : "f"(x)); return y;
}
// pre = KTANH*x. Returns r = 1/(exp(2x)+1); tanh(x) = 1 - 2r (affine folded
// into downstream weights). Saturates: x>>0 -> 0; x<<0 -> 1.
__device__ __forceinline__ float tanh_r(float pre) {
    return rcp_approx(ex2_approx(pre) + 1.0f);
}

__device__ __forceinline__ unsigned long long pack2(float lo, float hi) {
    unsigned long long r;
    asm("mov.b64 %0, {%1, %2};" : "=l"(r) : "f"(lo), "f"(hi)); return r;
}
__device__ __forceinline__ void unpack2(unsigned long long v, float& lo, float& hi) {
    asm("mov.b64 {%0, %1}, %2;" : "=f"(lo), "=f"(hi) : "l"(v));
}
__device__ __forceinline__ unsigned long long fma2(unsigned long long a,
                                                   unsigned long long b,
                                                   unsigned long long c) {
    unsigned long long d;
    asm("fma.rn.f32x2 %0, %1, %2, %3;" : "=l"(d) : "l"(a), "l"(b), "l"(c));
    return d;
}

__global__ __launch_bounds__(256, 1)
void reac_kernel(
    const float* __restrict__ u,    const float* __restrict__ xz0,
    const float* __restrict__ r1W0, const float* __restrict__ r1b0,
    const float* __restrict__ r1W1, const float* __restrict__ r1b1,
    const float* __restrict__ r1W2, const float* __restrict__ r1b2,
    const float* __restrict__ r2W0, const float* __restrict__ r2b0,
    const float* __restrict__ r2W1, const float* __restrict__ r2b1,
    const float* __restrict__ r2W2, const float* __restrict__ r2b2,
    const float* __restrict__ ymean, const float* __restrict__ ystd,
    const float* __restrict__ umean, const float* __restrict__ ustd,
    float* __restrict__ out)
{
    // sW1[0:256) = -2K*r1W1, sW1[256:512) = -2K*r2W1 (16x16 row-major each).
    __shared__ __align__(16) float sW1[512];
    const int tid = threadIdx.x;
    for (int k = tid; k < 256; k += 256) {
        sW1[k]       = -2.0f * KTANH * r1W1[k];
        sW1[k + 256] = -2.0f * KTANH * r2W1[k];
    }
    __syncthreads();

    const int g8   = tid & 7;            // lane within 8-lane element group
    const int half = (g8 >> 2) & 1;      // 0: r1 MLP, 1: r2 MLP
    const int g4   = (g8 & 3) * 4;       // hidden-unit base within own MLP
    const int e    = blockIdx.x * 32 + (tid >> 3);   // batch element

    const float* W0  = half ? r2W0 : r1W0;
    const float* B0  = half ? r2b0 : r1b0;
    const float* W1  = half ? r2W1 : r1W1;
    const float* B1  = half ? r2b1 : r1b1;
    const float* W2  = half ? r2W2 : r1W2;
    const float* B2  = half ? r2b2 : r1b2;

    // Per-lane folded weights for own MLP, hidden units [g4, g4+4).
    float wA[4], wB[4], b0K[4], w2m2[4], b1K[4];
    float base = 0.25f * B2[0];
    #pragma unroll
    for (int jj = 0; jj < 4; jj++) {
        const int j = g4 + jj;
        wA[jj]  = KTANH * W0[j];                     // times c0 (r1) / c1 (r2)
        wB[jj]  = half ? (KTANH * W0[16 + j]) : 0.0f; // times c2
        b0K[jj] = KTANH * B0[j];
        float cs = 0.0f;
        for (int i = 0; i < 16; i++) cs += W1[i * 16 + j];
        b1K[jj] = KTANH * (B1[j] + cs);
        const float w2 = W2[j];
        base += w2;
        w2m2[jj] = -2.0f * w2;
    }
    const unsigned long long b1p01 = pack2(b1K[0], b1K[1]);
    const unsigned long long b1p23 = pack2(b1K[2], b1K[3]);
    const int w1off = half * 256 + g4;   // + row*16 per iteration
    const int sbase = g8 & 4;            // shfl source offset for own half

    const float Castd = ystd[0], Cbstd = ystd[1];
    const float Camean = ymean[0], Cbmean = ymean[1];
    const float us = ustd[0], um = umean[0];
    // Normalized-coordinate dynamics:
    //   dCa = uc - 0.1*Ca - f1,  uc = ku*u + kc
    //   dCb = kb - 0.1*Cb + kr*f1 - 3*f2
    //   dCc = kb - 0.1*Cc + f2
    const float ku = 0.1f * us / Castd;
    const float kc = 0.1f * (um - Camean) / Castd;
    const float kb = -0.1f * Cbmean / Cbstd;
    const float kr = Castd / Cbstd;

    float x0 = xz0[e * 3 + 0], x1 = xz0[e * 3 + 1], x2 = xz0[e * 3 + 2];
    const float* ue = u + (size_t)e * TSEQ;
    float2* ybase = (float2*)(out + (size_t)e * TSEQ * 2);
    float* xbase = out + (size_t)BATCH * TSEQ * 2 + (size_t)e * TSEQ * 3;

    float uc = 0.0f;

    auto fxu = [&](float c0, float c1, float c2, float& d0, float& d1, float& d2) {
        // layer 0 of own MLP: input cA (+ cB*wB for r2; wB=0 for r1)
        const float cA = half ? c1 : c0;
        float h[4];
        #pragma unroll
        for (int jj = 0; jj < 4; jj++)
            h[jj] = tanh_r(fmaf(c2, wB[jj], fmaf(cA, wA[jj], b0K[jj])));
        // layer 1 matvec (FFMA2), shfl serves both halves via per-lane src
        unsigned long long acc01 = b1p01, acc23 = b1p23;
        #pragma unroll
        for (int s = 0; s < 4; s++) {
            #pragma unroll
            for (int r = 0; r < 4; r++) {
                const float v = __shfl_sync(0xffffffffu, h[r], s | sbase, 8);
                const unsigned long long vv = pack2(v, v);
                const ulonglong2 w = *(const ulonglong2*)(sW1 + w1off + (s * 4 + r) * 16);
                acc01 = fma2(vv, w.x, acc01);
                acc23 = fma2(vv, w.y, acc23);
            }
        }
        // layer 2 + quad reduction -> p (f1 on lanes 0-3, f2 on lanes 4-7)
        float a0, a1, a2, a3;
        unpack2(acc01, a0, a1); unpack2(acc23, a2, a3);
        float p = base;
        p = fmaf(tanh_r(a0), w2m2[0], p);
        p = fmaf(tanh_r(a1), w2m2[1], p);
        p = fmaf(tanh_r(a2), w2m2[2], p);
        p = fmaf(tanh_r(a3), w2m2[3], p);
        p += __shfl_xor_sync(0xffffffffu, p, 1, 8);
        p += __shfl_xor_sync(0xffffffffu, p, 2, 8);
        const float q = __shfl_xor_sync(0xffffffffu, p, 4, 8);
        const float f1 = half ? q : p;
        const float f2 = half ? p : q;
        d0 = fmaf(-0.1f, c0, uc) - f1;
        d1 = fmaf(kr, f1, fmaf(-3.0f, f2, fmaf(-0.1f, c1, kb)));
        d2 = fmaf(-0.1f, c2, kb) + f2;
    };

    #pragma unroll 1
    for (int t = 0; t < TSEQ; t++) {
        // Emit pre-update state (scan collects x_t before the step).
        if (g8 == 0)      ybase[t] = make_float2(x0, x1);
        else if (g8 == 1) xbase[t * 3 + 0] = x0;
        else if (g8 == 2) xbase[t * 3 + 1] = x1;
        else if (g8 == 3) xbase[t * 3 + 2] = x2;

        uc = fmaf(ku, __ldg(&ue[t]), kc);

        float a0, a1, a2, d0, d1, d2, s0, s1, s2;
        fxu(x0, x1, x2, a0, a1, a2);                               // k1
        s0 = fmaf(0.5f, a0, x0); s1 = fmaf(0.5f, a1, x1); s2 = fmaf(0.5f, a2, x2);
        fxu(s0, s1, s2, d0, d1, d2);                               // k2
        a0 = fmaf(2.0f, d0, a0); a1 = fmaf(2.0f, d1, a1); a2 = fmaf(2.0f, d2, a2);
        s0 = fmaf(0.5f, d0, x0); s1 = fmaf(0.5f, d1, x1); s2 = fmaf(0.5f, d2, x2);
        fxu(s0, s1, s2, d0, d1, d2);                               // k3
        a0 = fmaf(2.0f, d0, a0); a1 = fmaf(2.0f, d1, a1); a2 = fmaf(2.0f, d2, a2);
        s0 = x0 + d0; s1 = x1 + d1; s2 = x2 + d2;
        fxu(s0, s1, s2, d0, d1, d2);                               // k4
        a0 += d0; a1 += d1; a2 += d2;
        const float c6 = 1.0f / 6.0f;
        x0 = fmaf(c6, a0, x0); x1 = fmaf(c6, a1, x1); x2 = fmaf(c6, a2, x2);
    }
}

extern "C" void kernel_launch(void* const* d_in, const int* in_sizes, int n_in,
                              void* d_out, int out_size) {
    (void)in_sizes; (void)n_in; (void)out_size;
    reac_kernel<<<128, 256>>>(
        (const float*)d_in[0],  (const float*)d_in[1],
        (const float*)d_in[2],  (const float*)d_in[3],
        (const float*)d_in[4],  (const float*)d_in[5],
        (const float*)d_in[6],  (const float*)d_in[7],
        (const float*)d_in[8],  (const float*)d_in[9],
        (const float*)d_in[10], (const float*)d_in[11],
        (const float*)d_in[12], (const float*)d_in[13],
        (const float*)d_in[14], (const float*)d_in[15],
        (const float*)d_in[16], (const float*)d_in[17],
        (float*)d_out);
}

// round 4
// speedup vs baseline: 1.3151x; 1.3151x over previous
#include <cuda_runtime.h>

#define TSEQ 1024
#define BATCH 4096
#define KTANH 2.885390081777927f   // 2/ln(2): ex2(KTANH*x) = exp(2x)

__device__ __forceinline__ float ex2_approx(float x) {
    float y; asm("ex2.approx.f32 %0, %1;" : "=f"(y) : "f"(x)); return y;
}
__device__ __forceinline__ float rcp_approx(float x) {
    float y; asm("rcp.approx.f32 %0, %1;" : "=f"(y) : "f"(x)); return y;
}

// pre[j] = KTANH*x_j (clamped to <=30; tanh(x)=1-2e-9 there, so clamping is
// exact to fp32). Returns r_j = 1/(exp(2x_j)+1); tanh = 1 - 2r folded into
// downstream weights. One MUFU rcp serves all 4 lanes' values via the
// product trick: A0..A3 <= 2^30+1 so the quad product <= ~1.3e36 (no ovf).
__device__ __forceinline__ void tanh_quad(const float* pre, float* r) {
    const float A0 = ex2_approx(fminf(pre[0], 30.0f)) + 1.0f;
    const float A1 = ex2_approx(fminf(pre[1], 30.0f)) + 1.0f;
    const float A2 = ex2_approx(fminf(pre[2], 30.0f)) + 1.0f;
    const float A3 = ex2_approx(fminf(pre[3], 30.0f)) + 1.0f;
    const float m01 = A0 * A1, m23 = A2 * A3;
    const float rm  = rcp_approx(m01 * m23);
    const float r01 = rm * m23, r23 = rm * m01;
    r[0] = r01 * A1;  r[1] = r01 * A0;
    r[2] = r23 * A3;  r[3] = r23 * A2;
}

__device__ __forceinline__ unsigned long long pack2(float lo, float hi) {
    unsigned long long r;
    asm("mov.b64 %0, {%1, %2};" : "=l"(r) : "f"(lo), "f"(hi)); return r;
}
__device__ __forceinline__ void unpack2(unsigned long long v, float& lo, float& hi) {
    asm("mov.b64 {%0, %1}, %2;" : "=f"(lo), "=f"(hi) : "l"(v));
}
__device__ __forceinline__ unsigned long long fma2(unsigned long long a,
                                                   unsigned long long b,
                                                   unsigned long long c) {
    unsigned long long d;
    asm("fma.rn.f32x2 %0, %1, %2, %3;" : "=l"(d) : "l"(a), "l"(b), "l"(c));
    return d;
}
__device__ __forceinline__ unsigned long long add2(unsigned long long a,
                                                   unsigned long long b) {
    unsigned long long d;
    asm("add.rn.f32x2 %0, %1, %2;" : "=l"(d) : "l"(a), "l"(b));
    return d;
}

__global__ __launch_bounds__(128, 1)
void reac_kernel(
    const float* __restrict__ u,    const float* __restrict__ xz0,
    const float* __restrict__ r1W0, const float* __restrict__ r1b0,
    const float* __restrict__ r1W1, const float* __restrict__ r1b1,
    const float* __restrict__ r1W2, const float* __restrict__ r1b2,
    const float* __restrict__ r2W0, const float* __restrict__ r2b0,
    const float* __restrict__ r2W1, const float* __restrict__ r2b1,
    const float* __restrict__ r2W2, const float* __restrict__ r2b2,
    const float* __restrict__ ymean, const float* __restrict__ ystd,
    const float* __restrict__ umean, const float* __restrict__ ustd,
    float* __restrict__ out)
{
    // W1eff = -2*K*W1 (16x16 row-major [i][j]); broadcast LDS.128 reads.
    __shared__ __align__(16) float sW1a[256];
    __shared__ __align__(16) float sW1b[256];
    const int tid = threadIdx.x;
    for (int k = tid; k < 256; k += 128) {
        sW1a[k] = -2.0f * KTANH * r1W1[k];
        sW1b[k] = -2.0f * KTANH * r2W1[k];
    }
    __syncthreads();

    const int g  = tid & 3;                       // lane within 4-lane group
    const int g4 = g * 4;
    const int e  = blockIdx.x * 32 + (tid >> 2);  // batch element

    // Per-lane folded weights: lane g owns hidden units j in [4g, 4g+4).
    float w0aK[4], b0aK[4], w2m2a[4];
    float w0b0K[4], w0b1K[4], b0bK[4], w2m2b[4];
    float b1aK[4], b1bK[4];
    float basea = 0.25f * r1b2[0], baseb = 0.25f * r2b2[0];
    #pragma unroll
    for (int jj = 0; jj < 4; jj++) {
        const int j = g4 + jj;
        w0aK[jj]  = KTANH * r1W0[j];
        b0aK[jj]  = KTANH * r1b0[j];
        w0b0K[jj] = KTANH * r2W0[j];
        w0b1K[jj] = KTANH * r2W0[16 + j];
        b0bK[jj]  = KTANH * r2b0[j];
        float cs1 = 0.0f, cs2 = 0.0f;             // column sums of W1
        for (int i = 0; i < 16; i++) { cs1 += r1W1[i * 16 + j]; cs2 += r2W1[i * 16 + j]; }
        b1aK[jj] = KTANH * (r1b1[j] + cs1);
        b1bK[jj] = KTANH * (r2b1[j] + cs2);
        const float wa2 = r1W2[j], wb2 = r2W2[j];
        basea += wa2;  baseb += wb2;
        w2m2a[jj] = -2.0f * wa2;
        w2m2b[jj] = -2.0f * wb2;
    }
    const unsigned long long b1a01 = pack2(b1aK[0], b1aK[1]);
    const unsigned long long b1a23 = pack2(b1aK[2], b1aK[3]);
    const unsigned long long b1b01 = pack2(b1bK[0], b1bK[1]);
    const unsigned long long b1b23 = pack2(b1bK[2], b1bK[3]);

    const float Castd = ystd[0], Cbstd = ystd[1];
    const float Camean = ymean[0], Cbmean = ymean[1];
    const float us = ustd[0], um = umean[0];
    // Normalized-coordinate dynamics:
    //   dCa = uc - 0.1*Ca - f1,  uc = ku*u + kc
    //   dCb = kb - 0.1*Cb + kr*f1 - 3*f2
    //   dCc = kb - 0.1*Cc + f2
    const float ku = 0.1f * us / Castd;
    const float kc = 0.1f * (um - Camean) / Castd;
    const float kb = -0.1f * Cbmean / Cbstd;
    const float kr = Castd / Cbstd;

    float x0 = xz0[e * 3 + 0], x1 = xz0[e * 3 + 1], x2 = xz0[e * 3 + 2];
    const float* ue = u + (size_t)e * TSEQ;
    float2* ybase = (float2*)(out + (size_t)e * TSEQ * 2);
    float* xbase = out + (size_t)BATCH * TSEQ * 2 + (size_t)e * TSEQ * 3;

    float uc = 0.0f;

    auto fxu = [&](float c0, float c1, float c2, float& d0, float& d1, float& d2) {
        // layer 0 pre-activations (both MLPs), then quad-batched tanh
        float pa[4], pb[4], rh[4], sh[4];
        #pragma unroll
        for (int jj = 0; jj < 4; jj++) {
            pa[jj] = fmaf(c0, w0aK[jj], b0aK[jj]);
            pb[jj] = fmaf(c2, w0b1K[jj], fmaf(c1, w0b0K[jj], b0bK[jj]));
        }
        tanh_quad(pa, rh);
        tanh_quad(pb, sh);
        // fused layer-1 matvecs: FFMA2, 8 chains of depth 8 (split over s)
        unsigned long long accA01[2] = { b1a01, 0ull };
        unsigned long long accA23[2] = { b1a23, 0ull };
        unsigned long long accB01[2] = { b1b01, 0ull };
        unsigned long long accB23[2] = { b1b23, 0ull };
        #pragma unroll
        for (int s = 0; s < 4; s++) {
            const int c = s >> 1;
            #pragma unroll
            for (int r = 0; r < 4; r++) {
                const float v1 = __shfl_sync(0xffffffffu, rh[r], s, 4);
                const float v2 = __shfl_sync(0xffffffffu, sh[r], s, 4);
                const unsigned long long vv1 = pack2(v1, v1);
                const unsigned long long vv2 = pack2(v2, v2);
                const int row = (s * 4 + r) * 16 + g4;
                const ulonglong2 wa = *(const ulonglong2*)(sW1a + row);
                const ulonglong2 wb = *(const ulonglong2*)(sW1b + row);
                accA01[c] = fma2(vv1, wa.x, accA01[c]);
                accA23[c] = fma2(vv1, wa.y, accA23[c]);
                accB01[c] = fma2(vv2, wb.x, accB01[c]);
                accB23[c] = fma2(vv2, wb.y, accB23[c]);
            }
        }
        // layer 2: quad-batched tanh of accs, dot with w2eff, quad reduce
        float qa[4], qb[4], ta[4], tb[4];
        unpack2(add2(accA01[0], accA01[1]), qa[0], qa[1]);
        unpack2(add2(accA23[0], accA23[1]), qa[2], qa[3]);
        unpack2(add2(accB01[0], accB01[1]), qb[0], qb[1]);
        unpack2(add2(accB23[0], accB23[1]), qb[2], qb[3]);
        tanh_quad(qa, ta);
        tanh_quad(qb, tb);
        float p1 = basea, p2 = baseb;
        #pragma unroll
        for (int jj = 0; jj < 4; jj++) {
            p1 = fmaf(ta[jj], w2m2a[jj], p1);
            p2 = fmaf(tb[jj], w2m2b[jj], p2);
        }
        p1 += __shfl_xor_sync(0xffffffffu, p1, 1, 4);
        p2 += __shfl_xor_sync(0xffffffffu, p2, 1, 4);
        p1 += __shfl_xor_sync(0xffffffffu, p1, 2, 4);
        p2 += __shfl_xor_sync(0xffffffffu, p2, 2, 4);
        d0 = fmaf(-0.1f, c0, uc) - p1;
        d1 = fmaf(kr, p1, fmaf(-3.0f, p2, fmaf(-0.1f, c1, kb)));
        d2 = fmaf(-0.1f, c2, kb) + p2;
    };

    float ucur = __ldg(&ue[0]);

    #pragma unroll 1
    for (int t = 0; t < TSEQ; t++) {
        // Emit pre-update state (scan collects x_t before the step).
        if (g == 0)      ybase[t] = make_float2(x0, x1);
        else if (g == 1) xbase[t * 3 + 0] = x0;
        else if (g == 2) xbase[t * 3 + 1] = x1;
        else             xbase[t * 3 + 2] = x2;

        uc = fmaf(ku, ucur, kc);
        if (t + 1 < TSEQ) ucur = __ldg(&ue[t + 1]);   // prefetch next step

        float a0, a1, a2, d0, d1, d2, s0, s1, s2;
        fxu(x0, x1, x2, a0, a1, a2);                               // k1
        s0 = fmaf(0.5f, a0, x0); s1 = fmaf(0.5f, a1, x1); s2 = fmaf(0.5f, a2, x2);
        fxu(s0, s1, s2, d0, d1, d2);                               // k2
        a0 = fmaf(2.0f, d0, a0); a1 = fmaf(2.0f, d1, a1); a2 = fmaf(2.0f, d2, a2);
        s0 = fmaf(0.5f, d0, x0); s1 = fmaf(0.5f, d1, x1); s2 = fmaf(0.5f, d2, x2);
        fxu(s0, s1, s2, d0, d1, d2);                               // k3
        a0 = fmaf(2.0f, d0, a0); a1 = fmaf(2.0f, d1, a1); a2 = fmaf(2.0f, d2, a2);
        s0 = x0 + d0; s1 = x1 + d1; s2 = x2 + d2;
        fxu(s0, s1, s2, d0, d1, d2);                               // k4
        a0 += d0; a1 += d1; a2 += d2;
        const float c6 = 1.0f / 6.0f;
        x0 = fmaf(c6, a0, x0); x1 = fmaf(c6, a1, x1); x2 = fmaf(c6, a2, x2);
    }
}

extern "C" void kernel_launch(void* const* d_in, const int* in_sizes, int n_in,
                              void* d_out, int out_size) {
    (void)in_sizes; (void)n_in; (void)out_size;
    reac_kernel<<<128, 128>>>(
        (const float*)d_in[0],  (const float*)d_in[1],
        (const float*)d_in[2],  (const float*)d_in[3],
        (const float*)d_in[4],  (const float*)d_in[5],
        (const float*)d_in[6],  (const float*)d_in[7],
        (const float*)d_in[8],  (const float*)d_in[9],
        (const float*)d_in[10], (const float*)d_in[11],
        (const float*)d_in[12], (const float*)d_in[13],
        (const float*)d_in[14], (const float*)d_in[15],
        (const float*)d_in[16], (const float*)d_in[17],
        (float*)d_out);
}

// round 5
// speedup vs baseline: 1.7131x; 1.3026x over previous
#include <cuda_runtime.h>

#define TSEQ 1024
#define BATCH 4096

__device__ __forceinline__ float tanh_hw(float x) {
    float y; asm("tanh.approx.f32 %0, %1;" : "=f"(y) : "f"(x)); return y;
}

__device__ __forceinline__ unsigned long long pack2(float lo, float hi) {
    unsigned long long r;
    asm("mov.b64 %0, {%1, %2};" : "=l"(r) : "f"(lo), "f"(hi)); return r;
}
__device__ __forceinline__ void unpack2(unsigned long long v, float& lo, float& hi) {
    asm("mov.b64 {%0, %1}, %2;" : "=f"(lo), "=f"(hi) : "l"(v));
}
__device__ __forceinline__ unsigned long long fma2(unsigned long long a,
                                                   unsigned long long b,
                                                   unsigned long long c) {
    unsigned long long d;
    asm("fma.rn.f32x2 %0, %1, %2, %3;" : "=l"(d) : "l"(a), "l"(b), "l"(c));
    return d;
}
__device__ __forceinline__ unsigned long long add2(unsigned long long a,
                                                   unsigned long long b) {
    unsigned long long d;
    asm("add.rn.f32x2 %0, %1, %2;" : "=l"(d) : "l"(a), "l"(b));
    return d;
}

__global__ __launch_bounds__(128, 1)
void reac_kernel(
    const float* __restrict__ u,    const float* __restrict__ xz0,
    const float* __restrict__ r1W0, const float* __restrict__ r1b0,
    const float* __restrict__ r1W1, const float* __restrict__ r1b1,
    const float* __restrict__ r1W2, const float* __restrict__ r1b2,
    const float* __restrict__ r2W0, const float* __restrict__ r2b0,
    const float* __restrict__ r2W1, const float* __restrict__ r2b1,
    const float* __restrict__ r2W2, const float* __restrict__ r2b2,
    const float* __restrict__ ymean, const float* __restrict__ ystd,
    const float* __restrict__ umean, const float* __restrict__ ustd,
    float* __restrict__ out)
{
    // W1 (16x16 row-major [i][j]) in shared; broadcast LDS.128 reads.
    __shared__ __align__(16) float sW1a[256];
    __shared__ __align__(16) float sW1b[256];
    const int tid = threadIdx.x;
    for (int k = tid; k < 256; k += 128) { sW1a[k] = r1W1[k]; sW1b[k] = r2W1[k]; }
    __syncthreads();

    const int g  = tid & 3;                       // lane within 4-lane group
    const int g4 = g * 4;
    const int e  = blockIdx.x * 32 + (tid >> 2);  // batch element

    // Per-lane weight slices: lane g owns hidden units j in [4g, 4g+4).
    float w0a[4], b0a[4], w2a[4];
    float w0b0[4], w0b1[4], b0b[4], w2b[4];
    float b1a[4], b1b[4];
    #pragma unroll
    for (int jj = 0; jj < 4; jj++) {
        const int j = g4 + jj;
        w0a[jj]  = r1W0[j];       b0a[jj] = r1b0[j];
        w0b0[jj] = r2W0[j];       w0b1[jj] = r2W0[16 + j];
        b0b[jj]  = r2b0[j];
        b1a[jj]  = r1b1[j];       b1b[jj] = r2b1[j];
        w2a[jj]  = r1W2[j];       w2b[jj] = r2W2[j];
    }
    const float basea = 0.25f * r1b2[0], baseb = 0.25f * r2b2[0];
    const unsigned long long b1a01 = pack2(b1a[0], b1a[1]);
    const unsigned long long b1a23 = pack2(b1a[2], b1a[3]);
    const unsigned long long b1b01 = pack2(b1b[0], b1b[1]);
    const unsigned long long b1b23 = pack2(b1b[2], b1b[3]);

    const float Castd = ystd[0], Cbstd = ystd[1];
    const float Camean = ymean[0], Cbmean = ymean[1];
    const float us = ustd[0], um = umean[0];
    // Normalized-coordinate dynamics:
    //   dCa = uc - 0.1*Ca - f1,  uc = ku*u + kc
    //   dCb = kb - 0.1*Cb + kr*f1 - 3*f2
    //   dCc = kb - 0.1*Cc + f2
    const float ku = 0.1f * us / Castd;
    const float kc = 0.1f * (um - Camean) / Castd;
    const float kb = -0.1f * Cbmean / Cbstd;
    const float kr = Castd / Cbstd;

    float x0 = xz0[e * 3 + 0], x1 = xz0[e * 3 + 1], x2 = xz0[e * 3 + 2];
    const float* ue = u + (size_t)e * TSEQ;
    float2* ybase = (float2*)(out + (size_t)e * TSEQ * 2);
    float* xbase = out + (size_t)BATCH * TSEQ * 2 + (size_t)e * TSEQ * 3;

    float uc = 0.0f;

    auto fxu = [&](float c0, float c1, float c2, float& d0, float& d1, float& d2) {
        // layer 0 of both MLPs: 8 independent tanh chains (hardware tanh)
        float rh[4], sh[4];
        #pragma unroll
        for (int jj = 0; jj < 4; jj++) {
            rh[jj] = tanh_hw(fmaf(c0, w0a[jj], b0a[jj]));
            sh[jj] = tanh_hw(fmaf(c2, w0b1[jj], fmaf(c1, w0b0[jj], b0b[jj])));
        }
        // fused layer-1 matvecs: FFMA2, 8 chains split 2-way over s
        unsigned long long accA01[2] = { b1a01, 0ull };
        unsigned long long accA23[2] = { b1a23, 0ull };
        unsigned long long accB01[2] = { b1b01, 0ull };
        unsigned long long accB23[2] = { b1b23, 0ull };
        #pragma unroll
        for (int s = 0; s < 4; s++) {
            const int c = s >> 1;
            #pragma unroll
            for (int r = 0; r < 4; r++) {
                const float v1 = __shfl_sync(0xffffffffu, rh[r], s, 4);
                const float v2 = __shfl_sync(0xffffffffu, sh[r], s, 4);
                const unsigned long long vv1 = pack2(v1, v1);
                const unsigned long long vv2 = pack2(v2, v2);
                const int row = (s * 4 + r) * 16 + g4;
                const ulonglong2 wa = *(const ulonglong2*)(sW1a + row);
                const ulonglong2 wb = *(const ulonglong2*)(sW1b + row);
                accA01[c] = fma2(vv1, wa.x, accA01[c]);
                accA23[c] = fma2(vv1, wa.y, accA23[c]);
                accB01[c] = fma2(vv2, wb.x, accB01[c]);
                accB23[c] = fma2(vv2, wb.y, accB23[c]);
            }
        }
        // layer 2: hardware tanh + 2-chain dot + quad reduction
        float qa0, qa1, qa2, qa3, qb0, qb1, qb2, qb3;
        unpack2(add2(accA01[0], accA01[1]), qa0, qa1);
        unpack2(add2(accA23[0], accA23[1]), qa2, qa3);
        unpack2(add2(accB01[0], accB01[1]), qb0, qb1);
        unpack2(add2(accB23[0], accB23[1]), qb2, qb3);
        float pA = fmaf(tanh_hw(qa0), w2a[0], basea);
        float pB = tanh_hw(qa1) * w2a[1];
        float qA = fmaf(tanh_hw(qb0), w2b[0], baseb);
        float qB = tanh_hw(qb1) * w2b[1];
        pA = fmaf(tanh_hw(qa2), w2a[2], pA);
        pB = fmaf(tanh_hw(qa3), w2a[3], pB);
        qA = fmaf(tanh_hw(qb2), w2b[2], qA);
        qB = fmaf(tanh_hw(qb3), w2b[3], qB);
        float p1 = pA + pB, p2 = qA + qB;
        p1 += __shfl_xor_sync(0xffffffffu, p1, 1, 4);
        p2 += __shfl_xor_sync(0xffffffffu, p2, 1, 4);
        p1 += __shfl_xor_sync(0xffffffffu, p1, 2, 4);
        p2 += __shfl_xor_sync(0xffffffffu, p2, 2, 4);
        d0 = fmaf(-0.1f, c0, uc) - p1;
        d1 = fmaf(kr, p1, fmaf(-3.0f, p2, fmaf(-0.1f, c1, kb)));
        d2 = fmaf(-0.1f, c2, kb) + p2;
    };

    float ucur = __ldg(&ue[0]);

    #pragma unroll 1
    for (int t = 0; t < TSEQ; t++) {
        // Emit pre-update state (scan collects x_t before the step).
        if (g == 0)      ybase[t] = make_float2(x0, x1);
        else if (g == 1) xbase[t * 3 + 0] = x0;
        else if (g == 2) xbase[t * 3 + 1] = x1;
        else             xbase[t * 3 + 2] = x2;

        uc = fmaf(ku, ucur, kc);
        if (t + 1 < TSEQ) ucur = __ldg(&ue[t + 1]);   // prefetch next step

        float a0, a1, a2, d0, d1, d2, s0, s1, s2;
        fxu(x0, x1, x2, a0, a1, a2);                               // k1
        s0 = fmaf(0.5f, a0, x0); s1 = fmaf(0.5f, a1, x1); s2 = fmaf(0.5f, a2, x2);
        fxu(s0, s1, s2, d0, d1, d2);                               // k2
        a0 = fmaf(2.0f, d0, a0); a1 = fmaf(2.0f, d1, a1); a2 = fmaf(2.0f, d2, a2);
        s0 = fmaf(0.5f, d0, x0); s1 = fmaf(0.5f, d1, x1); s2 = fmaf(0.5f, d2, x2);
        fxu(s0, s1, s2, d0, d1, d2);                               // k3
        a0 = fmaf(2.0f, d0, a0); a1 = fmaf(2.0f, d1, a1); a2 = fmaf(2.0f, d2, a2);
        s0 = x0 + d0; s1 = x1 + d1; s2 = x2 + d2;
        fxu(s0, s1, s2, d0, d1, d2);                               // k4
        a0 += d0; a1 += d1; a2 += d2;
        const float c6 = 1.0f / 6.0f;
        x0 = fmaf(c6, a0, x0); x1 = fmaf(c6, a1, x1); x2 = fmaf(c6, a2, x2);
    }
}

extern "C" void kernel_launch(void* const* d_in, const int* in_sizes, int n_in,
                              void* d_out, int out_size) {
    (void)in_sizes; (void)n_in; (void)out_size;
    reac_kernel<<<128, 128>>>(
        (const float*)d_in[0],  (const float*)d_in[1],
        (const float*)d_in[2],  (const float*)d_in[3],
        (const float*)d_in[4],  (const float*)d_in[5],
        (const float*)d_in[6],  (const float*)d_in[7],
        (const float*)d_in[8],  (const float*)d_in[9],
        (const float*)d_in[10], (const float*)d_in[11],
        (const float*)d_in[12], (const float*)d_in[13],
        (const float*)d_in[14], (const float*)d_in[15],
        (const float*)d_in[16], (const float*)d_in[17],
        (float*)d_out);
}

// round 6
// speedup vs baseline: 2.1025x; 1.2273x over previous
#include <cuda_runtime.h>
#include <cuda_fp16.h>

#define TSEQ 1024
#define BATCH 4096

__device__ __forceinline__ unsigned tanh2u(unsigned x) {
    unsigned y; asm("tanh.approx.f16x2 %0, %1;" : "=r"(y) : "r"(x)); return y;
}
// pack (lo, hi) floats -> f16x2 (a goes to upper half in PTX cvt)
__device__ __forceinline__ unsigned cvtpack(float lo, float hi) {
    unsigned d; asm("cvt.rn.f16x2.f32 %0, %1, %2;" : "=r"(d) : "f"(hi), "f"(lo));
    return d;
}
__device__ __forceinline__ __half2 u2h(unsigned u) { return *reinterpret_cast<__half2*>(&u); }
__device__ __forceinline__ unsigned h2u(__half2 h) { return *reinterpret_cast<unsigned*>(&h); }

__global__ __launch_bounds__(128, 1)
void reac_kernel(
    const float* __restrict__ u,    const float* __restrict__ xz0,
    const float* __restrict__ r1W0, const float* __restrict__ r1b0,
    const float* __restrict__ r1W1, const float* __restrict__ r1b1,
    const float* __restrict__ r1W2, const float* __restrict__ r1b2,
    const float* __restrict__ r2W0, const float* __restrict__ r2b0,
    const float* __restrict__ r2W1, const float* __restrict__ r2b1,
    const float* __restrict__ r2W2, const float* __restrict__ r2b2,
    const float* __restrict__ ymean, const float* __restrict__ ystd,
    const float* __restrict__ umean, const float* __restrict__ ustd,
    float* __restrict__ out)
{
    // W1 in fp16, blocked for LDS.128: block b = ipair*4 + (j>>2) holds
    // 8 halfs: rows {2*ipair, 2*ipair+1} x cols {4gc..4gc+3}, row-major pairs:
    // [r0c0 r0c1 | r0c2 r0c3 | r1c0 r1c1 | r1c2 r1c3] = uint4 {x,y,z,w}.
    __shared__ __align__(16) __half sW1a[256];
    __shared__ __align__(16) __half sW1b[256];
    const int tid = threadIdx.x;
    for (int k = tid; k < 256; k += 128) {
        const int i = k >> 4, j = k & 15;
        const int idx = (((i >> 1) * 4 + (j >> 2)) << 3) + ((i & 1) << 2) + (j & 3);
        sW1a[idx] = __float2half(r1W1[k]);
        sW1b[idx] = __float2half(r2W1[k]);
    }
    __syncthreads();

    const int g  = tid & 3;                       // lane within 4-lane group
    const int g4 = g * 4;
    const int e  = blockIdx.x * 32 + (tid >> 2);  // batch element

    // Per-lane weight slices: lane g owns hidden units j in [4g, 4g+4).
    float w0a[4], b0a[4], w2a[4];
    float w0b0[4], w0b1[4], b0b[4], w2b[4];
    #pragma unroll
    for (int jj = 0; jj < 4; jj++) {
        const int j = g4 + jj;
        w0a[jj]  = r1W0[j];       b0a[jj] = r1b0[j];
        w0b0[jj] = r2W0[j];       w0b1[jj] = r2W0[16 + j];
        b0b[jj]  = r2b0[j];
        w2a[jj]  = r1W2[j];       w2b[jj] = r2W2[j];
    }
    const float basea = 0.25f * r1b2[0], baseb = 0.25f * r2b2[0];
    // layer-1 biases as half2 initial accumulators
    const __half2 b1a01 = __floats2half2_rn(r1b1[g4 + 0], r1b1[g4 + 1]);
    const __half2 b1a23 = __floats2half2_rn(r1b1[g4 + 2], r1b1[g4 + 3]);
    const __half2 b1b01 = __floats2half2_rn(r2b1[g4 + 0], r2b1[g4 + 1]);
    const __half2 b1b23 = __floats2half2_rn(r2b1[g4 + 2], r2b1[g4 + 3]);
    const __half2 hzero = __floats2half2_rn(0.0f, 0.0f);

    const float Castd = ystd[0], Cbstd = ystd[1];
    const float Camean = ymean[0], Cbmean = ymean[1];
    const float us = ustd[0], um = umean[0];
    // Normalized-coordinate dynamics:
    //   dCa = uc - 0.1*Ca - f1,  uc = ku*u + kc
    //   dCb = kb - 0.1*Cb + kr*f1 - 3*f2
    //   dCc = kb - 0.1*Cc + f2
    const float ku = 0.1f * us / Castd;
    const float kc = 0.1f * (um - Camean) / Castd;
    const float kb = -0.1f * Cbmean / Cbstd;
    const float kr = Castd / Cbstd;

    float x0 = xz0[e * 3 + 0], x1 = xz0[e * 3 + 1], x2 = xz0[e * 3 + 2];
    const float* ue = u + (size_t)e * TSEQ;
    float2* ybase = (float2*)(out + (size_t)e * TSEQ * 2);
    float* xbase = out + (size_t)BATCH * TSEQ * 2 + (size_t)e * TSEQ * 3;

    const uint4* W1Au = (const uint4*)sW1a;   // 32 blocks of 16B
    const uint4* W1Bu = (const uint4*)sW1b;

    float uc = 0.0f;

    auto fxu = [&](float c0, float c1, float c2, float& d0, float& d1, float& d2) {
        // layer 0 (fp32 FMA) -> pack -> hardware f16x2 tanh
        const float pa0 = fmaf(c0, w0a[0], b0a[0]);
        const float pa1 = fmaf(c0, w0a[1], b0a[1]);
        const float pa2 = fmaf(c0, w0a[2], b0a[2]);
        const float pa3 = fmaf(c0, w0a[3], b0a[3]);
        const float pb0 = fmaf(c2, w0b1[0], fmaf(c1, w0b0[0], b0b[0]));
        const float pb1 = fmaf(c2, w0b1[1], fmaf(c1, w0b0[1], b0b[1]));
        const float pb2 = fmaf(c2, w0b1[2], fmaf(c1, w0b0[2], b0b[2]));
        const float pb3 = fmaf(c2, w0b1[3], fmaf(c1, w0b0[3], b0b[3]));
        const unsigned hA0 = tanh2u(cvtpack(pa0, pa1));
        const unsigned hA1 = tanh2u(cvtpack(pa2, pa3));
        const unsigned hB0 = tanh2u(cvtpack(pb0, pb1));
        const unsigned hB1 = tanh2u(cvtpack(pb2, pb3));

        // layer 1: HFMA2 matvec, weights via LDS.128, h via half2 shfl.
        // 2-way split accumulators (even/odd s) for rounding + ILP.
        __half2 aA01[2] = { b1a01, hzero }, aA23[2] = { b1a23, hzero };
        __half2 aB01[2] = { b1b01, hzero }, aB23[2] = { b1b23, hzero };
        #pragma unroll
        for (int s = 0; s < 4; s++) {
            const int c = s & 1;
            const __half2 vA0 = u2h(__shfl_sync(0xffffffffu, hA0, s, 4));
            const __half2 vA1 = u2h(__shfl_sync(0xffffffffu, hA1, s, 4));
            const __half2 vB0 = u2h(__shfl_sync(0xffffffffu, hB0, s, 4));
            const __half2 vB1 = u2h(__shfl_sync(0xffffffffu, hB1, s, 4));
            const uint4 wa0 = W1Au[(2 * s) * 4 + g];       // rows 4s, 4s+1
            const uint4 wa1 = W1Au[(2 * s + 1) * 4 + g];   // rows 4s+2, 4s+3
            const uint4 wb0 = W1Bu[(2 * s) * 4 + g];
            const uint4 wb1 = W1Bu[(2 * s + 1) * 4 + g];
            aA01[c] = __hfma2(__low2half2(vA0),  u2h(wa0.x), aA01[c]);
            aA23[c] = __hfma2(__low2half2(vA0),  u2h(wa0.y), aA23[c]);
            aA01[c] = __hfma2(__high2half2(vA0), u2h(wa0.z), aA01[c]);
            aA23[c] = __hfma2(__high2half2(vA0), u2h(wa0.w), aA23[c]);
            aA01[c] = __hfma2(__low2half2(vA1),  u2h(wa1.x), aA01[c]);
            aA23[c] = __hfma2(__low2half2(vA1),  u2h(wa1.y), aA23[c]);
            aA01[c] = __hfma2(__high2half2(vA1), u2h(wa1.z), aA01[c]);
            aA23[c] = __hfma2(__high2half2(vA1), u2h(wa1.w), aA23[c]);
            aB01[c] = __hfma2(__low2half2(vB0),  u2h(wb0.x), aB01[c]);
            aB23[c] = __hfma2(__low2half2(vB0),  u2h(wb0.y), aB23[c]);
            aB01[c] = __hfma2(__high2half2(vB0), u2h(wb0.z), aB01[c]);
            aB23[c] = __hfma2(__high2half2(vB0), u2h(wb0.w), aB23[c]);
            aB01[c] = __hfma2(__low2half2(vB1),  u2h(wb1.x), aB01[c]);
            aB23[c] = __hfma2(__low2half2(vB1),  u2h(wb1.y), aB23[c]);
            aB01[c] = __hfma2(__high2half2(vB1), u2h(wb1.z), aB01[c]);
            aB23[c] = __hfma2(__high2half2(vB1), u2h(wb1.w), aB23[c]);
        }
        // layer 2: f16x2 tanh, fp32 dot with w2, quad reduction
        const float2 tA01 = __half22float2(u2h(tanh2u(h2u(__hadd2(aA01[0], aA01[1])))));
        const float2 tA23 = __half22float2(u2h(tanh2u(h2u(__hadd2(aA23[0], aA23[1])))));
        const float2 tB01 = __half22float2(u2h(tanh2u(h2u(__hadd2(aB01[0], aB01[1])))));
        const float2 tB23 = __half22float2(u2h(tanh2u(h2u(__hadd2(aB23[0], aB23[1])))));
        float pA = fmaf(tA01.x, w2a[0], basea);
        float pB = tA01.y * w2a[1];
        float qA = fmaf(tB01.x, w2b[0], baseb);
        float qB = tB01.y * w2b[1];
        pA = fmaf(tA23.x, w2a[2], pA);
        pB = fmaf(tA23.y, w2a[3], pB);
        qA = fmaf(tB23.x, w2b[2], qA);
        qB = fmaf(tB23.y, w2b[3], qB);
        float p1 = pA + pB, p2 = qA + qB;
        p1 += __shfl_xor_sync(0xffffffffu, p1, 1, 4);
        p2 += __shfl_xor_sync(0xffffffffu, p2, 1, 4);
        p1 += __shfl_xor_sync(0xffffffffu, p1, 2, 4);
        p2 += __shfl_xor_sync(0xffffffffu, p2, 2, 4);
        d0 = fmaf(-0.1f, c0, uc) - p1;
        d1 = fmaf(kr, p1, fmaf(-3.0f, p2, fmaf(-0.1f, c1, kb)));
        d2 = fmaf(-0.1f, c2, kb) + p2;
    };

    float ucur = __ldg(&ue[0]);

    #pragma unroll 1
    for (int t = 0; t < TSEQ; t++) {
        // Emit pre-update state (scan collects x_t before the step).
        if (g == 0)      ybase[t] = make_float2(x0, x1);
        else if (g == 1) xbase[t * 3 + 0] = x0;
        else if (g == 2) xbase[t * 3 + 1] = x1;
        else             xbase[t * 3 + 2] = x2;

        uc = fmaf(ku, ucur, kc);
        if (t + 1 < TSEQ) ucur = __ldg(&ue[t + 1]);   // prefetch next step

        float a0, a1, a2, d0, d1, d2, s0, s1, s2;
        fxu(x0, x1, x2, a0, a1, a2);                               // k1
        s0 = fmaf(0.5f, a0, x0); s1 = fmaf(0.5f, a1, x1); s2 = fmaf(0.5f, a2, x2);
        fxu(s0, s1, s2, d0, d1, d2);                               // k2
        a0 = fmaf(2.0f, d0, a0); a1 = fmaf(2.0f, d1, a1); a2 = fmaf(2.0f, d2, a2);
        s0 = fmaf(0.5f, d0, x0); s1 = fmaf(0.5f, d1, x1); s2 = fmaf(0.5f, d2, x2);
        fxu(s0, s1, s2, d0, d1, d2);                               // k3
        a0 = fmaf(2.0f, d0, a0); a1 = fmaf(2.0f, d1, a1); a2 = fmaf(2.0f, d2, a2);
        s0 = x0 + d0; s1 = x1 + d1; s2 = x2 + d2;
        fxu(s0, s1, s2, d0, d1, d2);                               // k4
        a0 += d0; a1 += d1; a2 += d2;
        const float c6 = 1.0f / 6.0f;
        x0 = fmaf(c6, a0, x0); x1 = fmaf(c6, a1, x1); x2 = fmaf(c6, a2, x2);
    }
}

extern "C" void kernel_launch(void* const* d_in, const int* in_sizes, int n_in,
                              void* d_out, int out_size) {
    (void)in_sizes; (void)n_in; (void)out_size;
    reac_kernel<<<128, 128>>>(
        (const float*)d_in[0],  (const float*)d_in[1],
        (const float*)d_in[2],  (const float*)d_in[3],
        (const float*)d_in[4],  (const float*)d_in[5],
        (const float*)d_in[6],  (const float*)d_in[7],
        (const float*)d_in[8],  (const float*)d_in[9],
        (const float*)d_in[10], (const float*)d_in[11],
        (const float*)d_in[12], (const float*)d_in[13],
        (const float*)d_in[14], (const float*)d_in[15],
        (const float*)d_in[16], (const float*)d_in[17],
        (float*)d_out);
}

// round 7
// speedup vs baseline: 2.3833x; 1.1335x over previous
#include <cuda_runtime.h>
#include <cuda_fp16.h>

#define TSEQ 1024
#define BATCH 4096

__device__ __forceinline__ unsigned tanh2u(unsigned x) {
    unsigned y; asm("tanh.approx.f16x2 %0, %1;" : "=r"(y) : "r"(x)); return y;
}
// pack (lo, hi) floats -> f16x2 (first PTX operand goes to upper half)
__device__ __forceinline__ unsigned cvtpack(float lo, float hi) {
    unsigned d; asm("cvt.rn.f16x2.f32 %0, %1, %2;" : "=r"(d) : "f"(hi), "f"(lo));
    return d;
}
__device__ __forceinline__ __half2 u2h(unsigned u) { return *reinterpret_cast<__half2*>(&u); }
__device__ __forceinline__ unsigned h2u(__half2 h) { return *reinterpret_cast<unsigned*>(&h); }

__global__ __launch_bounds__(128, 1)
void reac_kernel(
    const float* __restrict__ u,    const float* __restrict__ xz0,
    const float* __restrict__ r1W0, const float* __restrict__ r1b0,
    const float* __restrict__ r1W1, const float* __restrict__ r1b1,
    const float* __restrict__ r1W2, const float* __restrict__ r1b2,
    const float* __restrict__ r2W0, const float* __restrict__ r2b0,
    const float* __restrict__ r2W1, const float* __restrict__ r2b1,
    const float* __restrict__ r2W2, const float* __restrict__ r2b2,
    const float* __restrict__ ymean, const float* __restrict__ ystd,
    const float* __restrict__ umean, const float* __restrict__ ustd,
    float* __restrict__ out)
{
    const int tid = threadIdx.x;
    const int g  = tid & 3;                       // lane within 4-lane group
    const int g4 = g * 4;
    const int e  = blockIdx.x * 32 + (tid >> 2);  // batch element

    // Register-resident W1 slices (fp16): lane g holds all 16 rows x its 4
    // cols for both MLPs, as half2 pairs (cols 4g,4g+1) and (4g+2,4g+3).
    // 64 half2 = 64 regs; reused every fxu of every timestep (was LDS.128).
    __half2 wA01[16], wA23[16], wB01[16], wB23[16];
    #pragma unroll
    for (int i = 0; i < 16; i++) {
        wA01[i] = __floats2half2_rn(r1W1[i * 16 + g4 + 0], r1W1[i * 16 + g4 + 1]);
        wA23[i] = __floats2half2_rn(r1W1[i * 16 + g4 + 2], r1W1[i * 16 + g4 + 3]);
        wB01[i] = __floats2half2_rn(r2W1[i * 16 + g4 + 0], r2W1[i * 16 + g4 + 1]);
        wB23[i] = __floats2half2_rn(r2W1[i * 16 + g4 + 2], r2W1[i * 16 + g4 + 3]);
    }

    // Per-lane weight slices: lane g owns hidden units j in [4g, 4g+4).
    float w0a[4], b0a[4], w2a[4];
    float w0b0[4], w0b1[4], b0b[4], w2b[4];
    #pragma unroll
    for (int jj = 0; jj < 4; jj++) {
        const int j = g4 + jj;
        w0a[jj]  = r1W0[j];       b0a[jj] = r1b0[j];
        w0b0[jj] = r2W0[j];       w0b1[jj] = r2W0[16 + j];
        b0b[jj]  = r2b0[j];
        w2a[jj]  = r1W2[j];       w2b[jj] = r2W2[j];
    }
    const float basea = 0.25f * r1b2[0], baseb = 0.25f * r2b2[0];
    // layer-1 biases as half2 initial accumulators
    const __half2 b1a01 = __floats2half2_rn(r1b1[g4 + 0], r1b1[g4 + 1]);
    const __half2 b1a23 = __floats2half2_rn(r1b1[g4 + 2], r1b1[g4 + 3]);
    const __half2 b1b01 = __floats2half2_rn(r2b1[g4 + 0], r2b1[g4 + 1]);
    const __half2 b1b23 = __floats2half2_rn(r2b1[g4 + 2], r2b1[g4 + 3]);
    const __half2 hzero = __floats2half2_rn(0.0f, 0.0f);

    const float Castd = ystd[0], Cbstd = ystd[1];
    const float Camean = ymean[0], Cbmean = ymean[1];
    const float us = ustd[0], um = umean[0];
    // Normalized-coordinate dynamics:
    //   dCa = uc - 0.1*Ca - f1,  uc = ku*u + kc
    //   dCb = kb - 0.1*Cb + kr*f1 - 3*f2
    //   dCc = kb - 0.1*Cc + f2
    const float ku = 0.1f * us / Castd;
    const float kc = 0.1f * (um - Camean) / Castd;
    const float kb = -0.1f * Cbmean / Cbstd;
    const float kr = Castd / Cbstd;

    float x0 = xz0[e * 3 + 0], x1 = xz0[e * 3 + 1], x2 = xz0[e * 3 + 2];
    const float* ue = u + (size_t)e * TSEQ;
    float2* ybase = (float2*)(out + (size_t)e * TSEQ * 2);
    float* xbase = out + (size_t)BATCH * TSEQ * 2 + (size_t)e * TSEQ * 3;

    float uc = 0.0f;

    auto fxu = [&](float c0, float c1, float c2, float& d0, float& d1, float& d2) {
        // layer 0 (fp32 FMA) -> pack -> hardware f16x2 tanh
        const float pa0 = fmaf(c0, w0a[0], b0a[0]);
        const float pa1 = fmaf(c0, w0a[1], b0a[1]);
        const float pa2 = fmaf(c0, w0a[2], b0a[2]);
        const float pa3 = fmaf(c0, w0a[3], b0a[3]);
        const float pb0 = fmaf(c2, w0b1[0], fmaf(c1, w0b0[0], b0b[0]));
        const float pb1 = fmaf(c2, w0b1[1], fmaf(c1, w0b0[1], b0b[1]));
        const float pb2 = fmaf(c2, w0b1[2], fmaf(c1, w0b0[2], b0b[2]));
        const float pb3 = fmaf(c2, w0b1[3], fmaf(c1, w0b0[3], b0b[3]));
        const unsigned hA0 = tanh2u(cvtpack(pa0, pa1));
        const unsigned hA1 = tanh2u(cvtpack(pa2, pa3));
        const unsigned hB0 = tanh2u(cvtpack(pb0, pb1));
        const unsigned hB1 = tanh2u(cvtpack(pb2, pb3));

        // layer 1: HFMA2 matvec, weights in registers, h via half2 shfl.
        // 2-way split accumulators (even/odd s); ordering identical to R6.
        __half2 aA01[2] = { b1a01, hzero }, aA23[2] = { b1a23, hzero };
        __half2 aB01[2] = { b1b01, hzero }, aB23[2] = { b1b23, hzero };
        #pragma unroll
        for (int s = 0; s < 4; s++) {
            const int c = s & 1;
            const __half2 vA0 = u2h(__shfl_sync(0xffffffffu, hA0, s, 4));
            const __half2 vA1 = u2h(__shfl_sync(0xffffffffu, hA1, s, 4));
            const __half2 vB0 = u2h(__shfl_sync(0xffffffffu, hB0, s, 4));
            const __half2 vB1 = u2h(__shfl_sync(0xffffffffu, hB1, s, 4));
            aA01[c] = __hfma2(__low2half2(vA0),  wA01[4 * s + 0], aA01[c]);
            aA23[c] = __hfma2(__low2half2(vA0),  wA23[4 * s + 0], aA23[c]);
            aA01[c] = __hfma2(__high2half2(vA0), wA01[4 * s + 1], aA01[c]);
            aA23[c] = __hfma2(__high2half2(vA0), wA23[4 * s + 1], aA23[c]);
            aA01[c] = __hfma2(__low2half2(vA1),  wA01[4 * s + 2], aA01[c]);
            aA23[c] = __hfma2(__low2half2(vA1),  wA23[4 * s + 2], aA23[c]);
            aA01[c] = __hfma2(__high2half2(vA1), wA01[4 * s + 3], aA01[c]);
            aA23[c] = __hfma2(__high2half2(vA1), wA23[4 * s + 3], aA23[c]);
            aB01[c] = __hfma2(__low2half2(vB0),  wB01[4 * s + 0], aB01[c]);
            aB23[c] = __hfma2(__low2half2(vB0),  wB23[4 * s + 0], aB23[c]);
            aB01[c] = __hfma2(__high2half2(vB0), wB01[4 * s + 1], aB01[c]);
            aB23[c] = __hfma2(__high2half2(vB0), wB23[4 * s + 1], aB23[c]);
            aB01[c] = __hfma2(__low2half2(vB1),  wB01[4 * s + 2], aB01[c]);
            aB23[c] = __hfma2(__low2half2(vB1),  wB23[4 * s + 2], aB23[c]);
            aB01[c] = __hfma2(__high2half2(vB1), wB01[4 * s + 3], aB01[c]);
            aB23[c] = __hfma2(__high2half2(vB1), wB23[4 * s + 3], aB23[c]);
        }
        // layer 2: f16x2 tanh, fp32 dot with w2, quad reduction
        const float2 tA01 = __half22float2(u2h(tanh2u(h2u(__hadd2(aA01[0], aA01[1])))));
        const float2 tA23 = __half22float2(u2h(tanh2u(h2u(__hadd2(aA23[0], aA23[1])))));
        const float2 tB01 = __half22float2(u2h(tanh2u(h2u(__hadd2(aB01[0], aB01[1])))));
        const float2 tB23 = __half22float2(u2h(tanh2u(h2u(__hadd2(aB23[0], aB23[1])))));
        float pA = fmaf(tA01.x, w2a[0], basea);
        float pB = tA01.y * w2a[1];
        float qA = fmaf(tB01.x, w2b[0], baseb);
        float qB = tB01.y * w2b[1];
        pA = fmaf(tA23.x, w2a[2], pA);
        pB = fmaf(tA23.y, w2a[3], pB);
        qA = fmaf(tB23.x, w2b[2], qA);
        qB = fmaf(tB23.y, w2b[3], qB);
        float p1 = pA + pB, p2 = qA + qB;
        p1 += __shfl_xor_sync(0xffffffffu, p1, 1, 4);
        p2 += __shfl_xor_sync(0xffffffffu, p2, 1, 4);
        p1 += __shfl_xor_sync(0xffffffffu, p1, 2, 4);
        p2 += __shfl_xor_sync(0xffffffffu, p2, 2, 4);
        d0 = fmaf(-0.1f, c0, uc) - p1;
        d1 = fmaf(kr, p1, fmaf(-3.0f, p2, fmaf(-0.1f, c1, kb)));
        d2 = fmaf(-0.1f, c2, kb) + p2;
    };

    float ucur = __ldg(&ue[0]);

    #pragma unroll 1
    for (int t = 0; t < TSEQ; t++) {
        // Emit pre-update state (scan collects x_t before the step).
        if (g == 0)      ybase[t] = make_float2(x0, x1);
        else if (g == 1) xbase[t * 3 + 0] = x0;
        else if (g == 2) xbase[t * 3 + 1] = x1;
        else             xbase[t * 3 + 2] = x2;

        uc = fmaf(ku, ucur, kc);
        if (t + 1 < TSEQ) ucur = __ldg(&ue[t + 1]);   // prefetch next step

        float a0, a1, a2, d0, d1, d2, s0, s1, s2;
        fxu(x0, x1, x2, a0, a1, a2);                               // k1
        s0 = fmaf(0.5f, a0, x0); s1 = fmaf(0.5f, a1, x1); s2 = fmaf(0.5f, a2, x2);
        fxu(s0, s1, s2, d0, d1, d2);                               // k2
        a0 = fmaf(2.0f, d0, a0); a1 = fmaf(2.0f, d1, a1); a2 = fmaf(2.0f, d2, a2);
        s0 = fmaf(0.5f, d0, x0); s1 = fmaf(0.5f, d1, x1); s2 = fmaf(0.5f, d2, x2);
        fxu(s0, s1, s2, d0, d1, d2);                               // k3
        a0 = fmaf(2.0f, d0, a0); a1 = fmaf(2.0f, d1, a1); a2 = fmaf(2.0f, d2, a2);
        s0 = x0 + d0; s1 = x1 + d1; s2 = x2 + d2;
        fxu(s0, s1, s2, d0, d1, d2);                               // k4
        a0 += d0; a1 += d1; a2 += d2;
        const float c6 = 1.0f / 6.0f;
        x0 = fmaf(c6, a0, x0); x1 = fmaf(c6, a1, x1); x2 = fmaf(c6, a2, x2);
    }
}

extern "C" void kernel_launch(void* const* d_in, const int* in_sizes, int n_in,
                              void* d_out, int out_size) {
    (void)in_sizes; (void)n_in; (void)out_size;
    reac_kernel<<<128, 128>>>(
        (const float*)d_in[0],  (const float*)d_in[1],
        (const float*)d_in[2],  (const float*)d_in[3],
        (const float*)d_in[4],  (const float*)d_in[5],
        (const float*)d_in[6],  (const float*)d_in[7],
        (const float*)d_in[8],  (const float*)d_in[9],
        (const float*)d_in[10], (const float*)d_in[11],
        (const float*)d_in[12], (const float*)d_in[13],
        (const float*)d_in[14], (const float*)d_in[15],
        (const float*)d_in[16], (const float*)d_in[17],
        (float*)d_out);
}